// round 5
// baseline (speedup 1.0000x reference)
#include <cuda_runtime.h>

// Problem constants
#define T_STEPS 512
#define NBATCH  512
#define IN_DIM  64
#define H       100

// Layer-1 concatenated input [x(64) | h1(100) | pad] -> 176, quarters of 44
// Layer-2 concatenated input [h1(100) | h2(100) | pad] -> 208, quarters of 52
#define L1_LEN  176
#define L2_LEN  208
#define L1_Q    44
#define L2_Q    52

#define ROWS     4      // batch rows per CTA
#define NCTA     128    // 128 * 4 = 512 rows
#define NTHREADS 832    // 26 warps: 13 warps L1 (400 active), 13 warps L2 (400 active)
#define L2_BASE  416

// Transposed + concatenated + zero-padded weights (built once per launch by prep kernel)
__device__ float g_W1T[H * L1_LEN];   // [col j][k]  k: 0..63 = W1x[:,j], 64..163 = W1h[:,j], rest 0
__device__ float g_W2T[H * L2_LEN];   // [col j][k]  k: 0..99 = W2x[:,j], 100..199 = W2h[:,j], rest 0

__global__ void prep_kernel(const float* __restrict__ W1x, const float* __restrict__ W1h,
                            const float* __restrict__ W2x, const float* __restrict__ W2h) {
    int idx = blockIdx.x * blockDim.x + threadIdx.x;
    const int n1 = H * L1_LEN;
    if (idx < n1) {
        int j = idx / L1_LEN, k = idx % L1_LEN;
        float v = 0.0f;
        if (k < IN_DIM)           v = W1x[k * H + j];
        else if (k < IN_DIM + H)  v = W1h[(k - IN_DIM) * H + j];
        g_W1T[idx] = v;
    } else {
        int i2 = idx - n1;
        if (i2 < H * L2_LEN) {
            int j = i2 / L2_LEN, k = i2 % L2_LEN;
            float v = 0.0f;
            if (k < H)            v = W2x[k * H + j];
            else if (k < 2 * H)   v = W2h[(k - H) * H + j];
            g_W2T[i2] = v;
        }
    }
}

// Accurate-enough fast tanh: 1 - 2/(exp(2x)+1).  __expf = MUFU.EX2 path, rel err ~1e-6.
__device__ __forceinline__ float fast_tanh(float x) {
    float e = __expf(2.0f * x);
    return 1.0f - __fdividef(2.0f, e + 1.0f);
}

__global__ void __launch_bounds__(NTHREADS, 1)
rnn_kernel(const float* __restrict__ x,
           const float* __restrict__ b1, const float* __restrict__ b2,
           const float* __restrict__ Wo, const float* __restrict__ bo,
           float* __restrict__ out) {
    // Double-buffered per-row input vectors.
    // s_in1[buf][r] = [ x(t) (64) | h1(t-1) (100) | pad(12)=0 ]
    // s_in2[buf][r] = [ h1(t-1) (100) | h2(t-2) (100) | pad(8)=0 ]
    __shared__ __align__(16) float s_in1[2][ROWS][L1_LEN];
    __shared__ __align__(16) float s_in2[2][ROWS][L2_LEN];

    const int t  = threadIdx.x;
    const int b0 = blockIdx.x * ROWS;

    // Zero both buffers (pads stay 0 forever; h regions = h(-1)=0, h2(-2)=0).
    for (int i = t; i < 2 * ROWS * L1_LEN; i += NTHREADS) ((float*)s_in1)[i] = 0.0f;
    for (int i = t; i < 2 * ROWS * L2_LEN; i += NTHREADS) ((float*)s_in2)[i] = 0.0f;

    const bool isL1 = (t < L2_BASE);
    const float4* __restrict__ xg4 = (const float4*)x;
    const int pre_r = (t >> 4) & 3;   // x-prefetch mapping: 64 threads = 4 rows x 16 float4
    const int pre_d = t & 15;

    // Load this thread's weight slice into registers (k-split 4 per output column).
    float4 w4[L2_Q / 4];     // 13 float4 = 52 regs (L1 uses first 11)
    float  biasv = 0.0f;
    int jw, q;
    if (isL1) {
        jw = t >> 2; q = t & 3;
        int jc = jw < H ? jw : H - 1;
        const float4* wsrc = ((const float4*)g_W1T) + jc * (L1_LEN / 4) + q * (L1_Q / 4);
        #pragma unroll
        for (int i = 0; i < L1_Q / 4; ++i) w4[i] = wsrc[i];
        biasv = b1[jc];
    } else {
        int u = t - L2_BASE;
        jw = u >> 2; q = u & 3;
        int jc = jw < H ? jw : H - 1;
        const float4* wsrc = ((const float4*)g_W2T) + jc * (L2_LEN / 4) + q * (L2_Q / 4);
        #pragma unroll
        for (int i = 0; i < L2_Q / 4; ++i) w4[i] = wsrc[i];
        biasv = b2[jc];
    }

    __syncthreads();   // zero-fill visible before x(0) staging

    // Stage x(0) into buffer 0.
    if (t < 64) {
        float4 v = xg4[(b0 + pre_r) * (T_STEPS * (IN_DIM / 4)) + 0 * (IN_DIM / 4) + pre_d];
        ((float4*)&s_in1[0][pre_r][0])[pre_d] = v;
    }
    __syncthreads();

    // Pipelined phases: at phase p, L1 computes h1(p) (p<T), L2 computes h2(p-1) (p>=1).
    // All reads from buf (p&1), all writes to buf (p&1)^1; one barrier per phase.
    for (int p = 0; p <= T_STEPS; ++p) {
        const int pb = p & 1;

        // Prefetch x(p+1) (issued early, stored after compute).
        float4 xpre;
        const bool doPre = isL1 && (t < 64) && (p + 1 < T_STEPS);
        if (doPre)
            xpre = xg4[(b0 + pre_r) * (T_STEPS * (IN_DIM / 4)) + (p + 1) * (IN_DIM / 4) + pre_d];

        if (isL1) {
            if (p < T_STEPS) {
                #pragma unroll
                for (int r = 0; r < ROWS; ++r) {
                    const float4* v = ((const float4*)&s_in1[pb][r][0]) + q * (L1_Q / 4);
                    float4 a = make_float4(0.0f, 0.0f, 0.0f, 0.0f);
                    #pragma unroll
                    for (int i = 0; i < L1_Q / 4; ++i) {
                        float4 vv = v[i];
                        a.x = fmaf(w4[i].x, vv.x, a.x);
                        a.y = fmaf(w4[i].y, vv.y, a.y);
                        a.z = fmaf(w4[i].z, vv.z, a.z);
                        a.w = fmaf(w4[i].w, vv.w, a.w);
                    }
                    float red = (a.x + a.y) + (a.z + a.w);
                    red += __shfl_xor_sync(0xffffffffu, red, 1);
                    red += __shfl_xor_sync(0xffffffffu, red, 2);
                    if (q == 0 && jw < H) {
                        float h = fast_tanh(red + biasv);
                        s_in1[pb ^ 1][r][IN_DIM + jw] = h;   // next L1's h1(t-1)
                        s_in2[pb ^ 1][r][jw]          = h;   // next L2's h1(t-1)
                        if (p == T_STEPS - 1)
                            out[NBATCH + (b0 + r) * H + jw] = h;   // h1_T
                    }
                }
            }
        } else {
            if (p >= 1) {
                #pragma unroll
                for (int r = 0; r < ROWS; ++r) {
                    const float4* v = ((const float4*)&s_in2[pb][r][0]) + q * (L2_Q / 4);
                    float4 a = make_float4(0.0f, 0.0f, 0.0f, 0.0f);
                    #pragma unroll
                    for (int i = 0; i < L2_Q / 4; ++i) {
                        float4 vv = v[i];
                        a.x = fmaf(w4[i].x, vv.x, a.x);
                        a.y = fmaf(w4[i].y, vv.y, a.y);
                        a.z = fmaf(w4[i].z, vv.z, a.z);
                        a.w = fmaf(w4[i].w, vv.w, a.w);
                    }
                    float red = (a.x + a.y) + (a.z + a.w);
                    red += __shfl_xor_sync(0xffffffffu, red, 1);
                    red += __shfl_xor_sync(0xffffffffu, red, 2);
                    if (q == 0 && jw < H) {
                        float h = fast_tanh(red + biasv);
                        s_in2[pb ^ 1][r][H + jw] = h;        // next L2's h2(t-1)
                        if (p == T_STEPS)
                            out[NBATCH + NBATCH * H + (b0 + r) * H + jw] = h;   // h2_T
                    }
                }
            }
        }

        if (doPre)
            ((float4*)&s_in1[pb ^ 1][pre_r][0])[pre_d] = xpre;

        __syncthreads();
    }

    // out = h2_T @ Wo + bo.  h2(T-1) was written at phase 512 (pb=0) into buffer 1.
    if (t < ROWS) {
        float acc = bo[0];
        #pragma unroll 4
        for (int k = 0; k < H; ++k)
            acc = fmaf(s_in2[1][t][H + k], Wo[k], acc);
        out[b0 + t] = acc;
    }
}

extern "C" void kernel_launch(void* const* d_in, const int* in_sizes, int n_in,
                              void* d_out, int out_size) {
    const float* x   = (const float*)d_in[0];
    const float* W1x = (const float*)d_in[1];
    const float* W1h = (const float*)d_in[2];
    const float* b1  = (const float*)d_in[3];
    const float* W2x = (const float*)d_in[4];
    const float* W2h = (const float*)d_in[5];
    const float* b2  = (const float*)d_in[6];
    const float* Wo  = (const float*)d_in[7];
    const float* bo  = (const float*)d_in[8];
    float* out = (float*)d_out;

    // Build transposed/padded weight images (38400 elements total).
    prep_kernel<<<150, 256>>>(W1x, W1h, W2x, W2h);

    // Persistent batch-partitioned RNN: 128 CTAs x 4 rows, no inter-CTA sync.
    rnn_kernel<<<NCTA, NTHREADS>>>(x, b1, b2, Wo, bo, out);
}